// round 16
// baseline (speedup 1.0000x reference)
#include <cuda_runtime.h>

#define Bn 64
#define Cn 8
#define Nn 2048
#define Tn 64
#define CH 8                    // i-chunks per (b,c) plane in k_reduce
#define PLANE4 (Nn * Tn / 4)    // 32768 float4 per (b,c) plane

// Scratch (no allocations allowed)
__device__ float g_kp[Bn * Cn * CH * Tn];  // partial k sums, 1 MB

// ---------------------------------------------------------------------------
// Kernel 1: partial k: g_kp[bc][ch][t] = sum_{i in chunk ch} alpha[i]*x[b,c,i,t]
// grid = B*C*CH = 4096 blocks, 256 threads: 16 t4-lanes x 16 i-rows.
// Alpha staged in smem; fully unrolled 16-load body; FOUR accumulator chains.
// ---------------------------------------------------------------------------
__global__ void __launch_bounds__(256) k_reduce(const float* __restrict__ x,
                                                const float* __restrict__ alpha) {
    int blk = blockIdx.x;                  // 0..4095
    int bc  = blk >> 3;                    // (b,c) plane
    int ch  = blk & (CH - 1);
    int i0  = ch * (Nn / CH);              // 256-row chunk base

    const float4* __restrict__ xp =
        (const float4*)x + (size_t)bc * PLANE4 + (size_t)i0 * (Tn / 4);
    int tid  = threadIdx.x;
    int lane = tid & 15;                   // t4 index
    int row  = tid >> 4;                   // i-row group (16)

    __shared__ float sa[Nn / CH];
    sa[tid] = __ldg(alpha + i0 + tid);
    __syncthreads();

    // 16 i-rows per thread: 4 iterations x 4 independent streams
    float4 acc0 = make_float4(0.f, 0.f, 0.f, 0.f);
    float4 acc1 = make_float4(0.f, 0.f, 0.f, 0.f);
    float4 acc2 = make_float4(0.f, 0.f, 0.f, 0.f);
    float4 acc3 = make_float4(0.f, 0.f, 0.f, 0.f);
    #pragma unroll
    for (int it = 0; it < 4; it++) {
        int ia = it * 64 + row;
        float  a0 = sa[ia];
        float  a1 = sa[ia + 16];
        float  a2 = sa[ia + 32];
        float  a3 = sa[ia + 48];
        float4 v0 = __ldcg(xp + ia * 16 + lane);
        float4 v1 = __ldcg(xp + (ia + 16) * 16 + lane);
        float4 v2 = __ldcg(xp + (ia + 32) * 16 + lane);
        float4 v3 = __ldcg(xp + (ia + 48) * 16 + lane);
        acc0.x += a0 * v0.x; acc0.y += a0 * v0.y;
        acc0.z += a0 * v0.z; acc0.w += a0 * v0.w;
        acc1.x += a1 * v1.x; acc1.y += a1 * v1.y;
        acc1.z += a1 * v1.z; acc1.w += a1 * v1.w;
        acc2.x += a2 * v2.x; acc2.y += a2 * v2.y;
        acc2.z += a2 * v2.z; acc2.w += a2 * v2.w;
        acc3.x += a3 * v3.x; acc3.y += a3 * v3.y;
        acc3.z += a3 * v3.z; acc3.w += a3 * v3.w;
    }
    acc0.x += acc1.x; acc0.y += acc1.y; acc0.z += acc1.z; acc0.w += acc1.w;
    acc2.x += acc3.x; acc2.y += acc3.y; acc2.z += acc3.z; acc2.w += acc3.w;
    acc0.x += acc2.x; acc0.y += acc2.y; acc0.z += acc2.z; acc0.w += acc2.w;

    __shared__ float4 s[16][16];
    s[row][lane] = acc0;
    __syncthreads();
    for (int str = 8; str >= 1; str >>= 1) {
        if (row < str) {
            float4 o = s[row + str][lane];
            float4 m = s[row][lane];
            m.x += o.x; m.y += o.y; m.z += o.z; m.w += o.w;
            s[row][lane] = m;
        }
        __syncthreads();
    }
    if (row == 0) {
        ((float4*)(g_kp + (size_t)blk * Tn))[lane] = s[0][lane];
    }
}

// ---------------------------------------------------------------------------
// Kernel 2 (FUSED): per-block prologue computes att[b] from g_kp (redundant
// per block; g_kp + Wc are L2-resident so this adds ~no DRAM traffic), then
// streams: out[b,c,n,t] = sum_d att[b,c,d] * x[b,d,n,t].
// grid = B*64 blocks, 256 threads; 2 float4 positions/thread.
// ---------------------------------------------------------------------------
__global__ void __launch_bounds__(256) k_agg(const float* __restrict__ x,
                                             const float* __restrict__ Wc,
                                             float* __restrict__ out) {
    int b  = blockIdx.x >> 6;
    int pb = blockIdx.x & 63;
    int p  = pb * 512 + threadIdx.x;
    int tid = threadIdx.x;

    __shared__ float ks[Cn][Tn];
    __shared__ float kW[Cn][Tn];
    __shared__ float sc[Cn][Cn];
    __shared__ float att[Cn * Cn];

    // --- prologue: att[b] from partial k sums ---
    for (int idx = tid; idx < Cn * Tn; idx += 256) {
        int c = idx / Tn, t = idx % Tn;
        const float* q = g_kp + (((size_t)(b * Cn + c)) * CH) * Tn + t;
        float acc = 0.f;
        #pragma unroll
        for (int h = 0; h < CH; h++) acc += __ldg(q + h * Tn);
        ks[c][t] = acc;
    }
    __syncthreads();

    for (int idx = tid; idx < Cn * Tn; idx += 256) {
        int c = idx >> 6, s = idx & 63;
        float acc = 0.f;
        #pragma unroll 8
        for (int t = 0; t < Tn; t++)
            acc += ks[c][t] * __ldg(Wc + t * Tn + s);
        kW[c][s] = acc;
    }
    __syncthreads();

    if (tid < Cn * Cn) {
        int c = tid >> 3, d = tid & 7;
        float sco = 0.f;
        #pragma unroll 8
        for (int ss = 0; ss < Tn; ss++)
            sco += kW[c][ss] * ks[d][ss];
        sc[c][d] = sco;
    }
    __syncthreads();

    if (tid < Cn * Cn) {
        int c = tid >> 3;
        float m = -1e30f;
        #pragma unroll
        for (int j = 0; j < Cn; j++) m = fmaxf(m, sc[c][j]);
        float den = 0.f;
        #pragma unroll
        for (int j = 0; j < Cn; j++) den += expf(sc[c][j] - m);
        att[tid] = expf(sc[c][tid & 7] - m) / den;
    }
    __syncthreads();

    // --- streaming body ---
    const float4* __restrict__ xp =
        (const float4*)x + (size_t)b * Cn * PLANE4 + p;
    float4* __restrict__ op =
        (float4*)out + (size_t)b * Cn * PLANE4 + p;

    float4 xv0[Cn], xv1[Cn];
    #pragma unroll
    for (int d = 0; d < Cn; d++) {
        xv0[d] = __ldcs(xp + (size_t)d * PLANE4);
        xv1[d] = __ldcs(xp + (size_t)d * PLANE4 + 256);
    }

    #pragma unroll
    for (int c = 0; c < Cn; c++) {
        float4 a0 = make_float4(0.f, 0.f, 0.f, 0.f);
        float4 a1 = make_float4(0.f, 0.f, 0.f, 0.f);
        #pragma unroll
        for (int d = 0; d < Cn; d++) {
            float a = att[c * Cn + d];
            a0.x += a * xv0[d].x; a0.y += a * xv0[d].y;
            a0.z += a * xv0[d].z; a0.w += a * xv0[d].w;
            a1.x += a * xv1[d].x; a1.y += a * xv1[d].y;
            a1.z += a * xv1[d].z; a1.w += a * xv1[d].w;
        }
        __stcs(op + (size_t)c * PLANE4, a0);
        __stcs(op + (size_t)c * PLANE4 + 256, a1);
    }
}

// ---------------------------------------------------------------------------
extern "C" void kernel_launch(void* const* d_in, const int* in_sizes, int n_in,
                              void* d_out, int out_size) {
    const float* x     = (const float*)d_in[0];
    const float* Wc    = (const float*)d_in[1];
    const float* alpha = (const float*)d_in[2];
    float* out         = (float*)d_out;

    k_reduce<<<Bn * Cn * CH, 256>>>(x, alpha);
    k_agg<<<Bn * 64, 256>>>(x, Wc, out);
}